// round 8
// baseline (speedup 1.0000x reference)
#include <cuda_runtime.h>
#include <cuda_bf16.h>
#include <cuda_fp16.h>
#include <cstdint>

#define NN 50000
#define NN_PAD 50048          // 391 * 128
#define EE 600000
#define DH 128
#define SCAN_G 49             // 49 * 1024 = 50176 >= NN

// -------- device scratch (no allocations allowed) --------
__device__ __half g_xwh[NN * DH];               // dinv-scaled A@W, fp16
__device__ float g_dinv[NN];
__device__ int   g_count[NN];
__device__ int   g_off[NN + 1];
__device__ int   g_cursor[NN];
__device__ int   g_csr[EE];
__device__ int   g_bsum[SCAN_G];
__device__ int   g_bbase[SCAN_G];
__device__ int   g_tick;
__device__ float g_p[NN * 8];
__device__ __nv_bfloat16 g_ahi[NN_PAD * DH];    // bf16 split of current GEMM input
__device__ __nv_bfloat16 g_alo[NN_PAD * DH];
__device__ __nv_bfloat16 g_b1hi[DH * DH];       // bf16 split of W1^T / W2^T
__device__ __nv_bfloat16 g_b1lo[DH * DH];
__device__ __nv_bfloat16 g_b2hi[DH * DH];
__device__ __nv_bfloat16 g_b2lo[DH * DH];

__device__ __forceinline__ uint32_t smem_u32(const void* p) {
    uint32_t a;
    asm("{ .reg .u64 t; cvta.to.shared.u64 t, %1; cvt.u32.u64 %0, t; }" : "=r"(a) : "l"(p));
    return a;
}

// -------- fused prep: x -> bf16 split, W1/W2 -> transposed bf16 split, zero counts --------
__global__ void k_prep(const float4* __restrict__ x4,
                       const float* __restrict__ W1, const float* __restrict__ W2, int n) {
    int i = blockIdx.x * blockDim.x + threadIdx.x;
    if (i < NN) g_count[i] = 0;
    if (i < 2 * DH * DH) {
        int which = i >> 14;
        int j = i & 16383;
        int nIdx = j >> 7, k = j & 127;
        const float* W = which ? W2 : W1;
        float v = W[k * DH + nIdx];               // transpose: B[n][k] = W[k][n]
        __nv_bfloat16 h = __float2bfloat16(v);
        __nv_bfloat16 l = __float2bfloat16(v - __bfloat162float(h));
        if (which) { g_b2hi[j] = h; g_b2lo[j] = l; }
        else       { g_b1hi[j] = h; g_b1lo[j] = l; }
    }
    if (i >= NN_PAD * 32) return;
    int row = i >> 5;
    float4 v = (row < n) ? x4[i] : make_float4(0.f, 0.f, 0.f, 0.f);
    __nv_bfloat162 h01 = __floats2bfloat162_rn(v.x, v.y);
    __nv_bfloat162 h23 = __floats2bfloat162_rn(v.z, v.w);
    float2 f01 = __bfloat1622float2(h01);
    float2 f23 = __bfloat1622float2(h23);
    __nv_bfloat162 l01 = __floats2bfloat162_rn(v.x - f01.x, v.y - f01.y);
    __nv_bfloat162 l23 = __floats2bfloat162_rn(v.z - f23.x, v.w - f23.y);
    __nv_bfloat162* ah = (__nv_bfloat162*)g_ahi;
    __nv_bfloat162* al = (__nv_bfloat162*)g_alo;
    ah[i * 2] = h01; ah[i * 2 + 1] = h23;
    al[i * 2] = l01; al[i * 2 + 1] = l23;
}

// -------- CSR construction (4 edges per thread for MLP) --------
__global__ void k_hist(const int4* __restrict__ col4, int E4) {
    int i = blockIdx.x * blockDim.x + threadIdx.x;
    if (i < E4) {
        int4 c = col4[i];
        atomicAdd(&g_count[c.x], 1);
        atomicAdd(&g_count[c.y], 1);
        atomicAdd(&g_count[c.z], 1);
        atomicAdd(&g_count[c.w], 1);
    }
}

// block sums + last-block scan of the 49 block sums (fused)
__global__ void k_bsum(int n) {
    __shared__ int sh[1024];
    int tid = threadIdx.x;
    int i = blockIdx.x * 1024 + tid;
    sh[tid] = (i < n) ? g_count[i] : 0;
    __syncthreads();
#pragma unroll
    for (int o = 512; o > 0; o >>= 1) {
        if (tid < o) sh[tid] += sh[tid + o];
        __syncthreads();
    }
    if (tid == 0) {
        g_bsum[blockIdx.x] = sh[0];
        __threadfence();
        int t = atomicAdd(&g_tick, 1);
        if (t == SCAN_G - 1) {
            g_tick = 0;                       // reset for next graph replay
            int run = 0;
            for (int b = 0; b < SCAN_G; b++) { g_bbase[b] = run; run += g_bsum[b]; }
        }
    }
}

__global__ void k_scan2(int n) {
    __shared__ int sh[1024];
    int tid = threadIdx.x;
    int i = blockIdx.x * 1024 + tid;
    int v = (i < n) ? g_count[i] : 0;
    sh[tid] = v;
    __syncthreads();
#pragma unroll
    for (int o = 1; o < 1024; o <<= 1) {
        int t = (tid >= o) ? sh[tid - o] : 0;
        __syncthreads();
        sh[tid] += t;
        __syncthreads();
    }
    if (i < n) {
        int excl = g_bbase[blockIdx.x] + sh[tid] - v;
        g_off[i] = excl;
        g_cursor[i] = excl;
        g_dinv[i] = rsqrtf((float)(v + 1));
        if (i == n - 1) g_off[n] = excl + v;
    }
}

__global__ void k_scatter(const int4* __restrict__ row4, const int4* __restrict__ col4, int E4) {
    int i = blockIdx.x * blockDim.x + threadIdx.x;
    if (i < E4) {
        int4 c = col4[i];
        int4 r = row4[i];
        g_csr[atomicAdd(&g_cursor[c.x], 1)] = r.x;
        g_csr[atomicAdd(&g_cursor[c.y], 1)] = r.y;
        g_csr[atomicAdd(&g_cursor[c.z], 1)] = r.z;
        g_csr[atomicAdd(&g_cursor[c.w], 1)] = r.w;
    }
}

// ======================= mma.sync (HMMA) GEMM =======================
// xwh[row,:] = fp16( dinv[row] * (A[row,:] @ W) ) via 3-pass bf16 split.
#define SM_AHI  0
#define SM_ALO  32768
#define SM_BHI  65536
#define SM_BLO  98304
#define SM_TOTAL 131072

__device__ __forceinline__ void ldm_x4(uint32_t* r, uint32_t addr) {
    asm volatile("ldmatrix.sync.aligned.m8n8.x4.shared.b16 {%0,%1,%2,%3}, [%4];"
                 : "=r"(r[0]), "=r"(r[1]), "=r"(r[2]), "=r"(r[3]) : "r"(addr) : "memory");
}
__device__ __forceinline__ void mma16816(float* c, const uint32_t* a, const uint32_t* b) {
    asm volatile("mma.sync.aligned.m16n8k16.row.col.f32.bf16.bf16.f32 "
                 "{%0,%1,%2,%3}, {%4,%5,%6,%7}, {%8,%9}, {%0,%1,%2,%3};"
                 : "+f"(c[0]), "+f"(c[1]), "+f"(c[2]), "+f"(c[3])
                 : "r"(a[0]), "r"(a[1]), "r"(a[2]), "r"(a[3]), "r"(b[0]), "r"(b[1]));
}
__device__ __forceinline__ uint32_t sw_off(int row, int chunk) {
    int phys = (chunk & 8) | ((chunk ^ row) & 7);
    return (uint32_t)(row * 256 + phys * 16);
}

__global__ void __launch_bounds__(256, 1) k_gemm_mma(
        __half* __restrict__ C,
        const __nv_bfloat16* __restrict__ bhi,
        const __nv_bfloat16* __restrict__ blo, int n) {
    extern __shared__ char smem[];
    uint32_t sb = smem_u32(smem);
    int tid = threadIdx.x, wid = tid >> 5, lane = tid & 31;
    int row0 = blockIdx.x * 128;

    {
        const __nv_bfloat16* srcs[4] = { g_ahi + (size_t)row0 * DH, g_alo + (size_t)row0 * DH,
                                         bhi, blo };
        const int bases[4] = { SM_AHI, SM_ALO, SM_BHI, SM_BLO };
#pragma unroll
        for (int t4 = 0; t4 < 4; t4++) {
            const uint4* src = (const uint4*)srcs[t4];
#pragma unroll
            for (int j = 0; j < 8; j++) {
                int f = tid + 256 * j;          // 0..2047
                int row = f >> 4;
                int chunk = f & 15;
                *(uint4*)(smem + bases[t4] + sw_off(row, chunk)) = src[row * 16 + chunk];
            }
        }
    }
    __syncthreads();

    int warp_m = wid & 3;
    int warp_n = wid >> 2;
    int lr = lane & 7;
    int rowA0 = warp_m * 32 + ((lane >> 3) & 1) * 8 + lr;
    int aHi = lane >> 4;
    int rowB0 = warp_n * 64 + ((lane >> 4) & 1) * 8 + lr;
    int bHi = (lane >> 3) & 1;

    float c[2][8][4];
#pragma unroll
    for (int mt = 0; mt < 2; mt++)
#pragma unroll
        for (int nt = 0; nt < 8; nt++)
#pragma unroll
            for (int q = 0; q < 4; q++) c[mt][nt][q] = 0.f;

#pragma unroll
    for (int p = 0; p < 3; p++) {
        uint32_t aBase = sb + (p == 2 ? SM_ALO : SM_AHI);
        uint32_t bBase = sb + (p == 1 ? SM_BLO : SM_BHI);
#pragma unroll
        for (int ks = 0; ks < 8; ks++) {
            uint32_t a[2][4];
#pragma unroll
            for (int mt = 0; mt < 2; mt++)
                ldm_x4(a[mt], aBase + sw_off(rowA0 + mt * 16, ks * 2 + aHi));
            uint32_t b[8][2];
#pragma unroll
            for (int nt2 = 0; nt2 < 4; nt2++) {
                uint32_t r[4];
                ldm_x4(r, bBase + sw_off(rowB0 + nt2 * 16, ks * 2 + bHi));
                b[2 * nt2][0] = r[0]; b[2 * nt2][1] = r[1];
                b[2 * nt2 + 1][0] = r[2]; b[2 * nt2 + 1][1] = r[3];
            }
#pragma unroll
            for (int mt = 0; mt < 2; mt++)
#pragma unroll
                for (int nt = 0; nt < 8; nt++)
                    mma16816(c[mt][nt], a[mt], b[nt]);
        }
    }

#pragma unroll
    for (int mt = 0; mt < 2; mt++) {
        int row = row0 + warp_m * 32 + mt * 16 + (lane >> 2);
        int col = warp_n * 64 + (lane & 3) * 2;
        float s0 = (row < n) ? g_dinv[row] : 0.f;
        float s1 = (row + 8 < n) ? g_dinv[row + 8] : 0.f;
#pragma unroll
        for (int nt = 0; nt < 8; nt++) {
            int cc = col + nt * 8;
            if (row < n)
                *(__half2*)&C[(size_t)row * DH + cc] =
                    __floats2half2_rn(c[mt][nt][0] * s0, c[mt][nt][1] * s0);
            if (row + 8 < n)
                *(__half2*)&C[(size_t)(row + 8) * DH + cc] =
                    __floats2half2_rn(c[mt][nt][2] * s1, c[mt][nt][3] * s1);
        }
    }
}

// -------- aggregation core: one warp per node, fp16 rows, fp32 accum --------
__device__ __forceinline__ float4 agg_node(const uint2* __restrict__ xwh, int c, int lane) {
    uint2 sv = xwh[c * 32 + lane];                 // self-loop term
    float2 a01 = __half22float2(*(__half2*)&sv.x);
    float2 a23 = __half22float2(*(__half2*)&sv.y);
    float4 acc = make_float4(a01.x, a01.y, a23.x, a23.y);
    int s = g_off[c], e = g_off[c + 1];
    int k = s;
    for (; k + 8 <= e; k += 8) {
        int r[8];
#pragma unroll
        for (int j = 0; j < 8; j++) r[j] = g_csr[k + j];
        uint2 v[8];
#pragma unroll
        for (int j = 0; j < 8; j++) v[j] = xwh[r[j] * 32 + lane];
#pragma unroll
        for (int j = 0; j < 8; j++) {
            float2 f01 = __half22float2(*(__half2*)&v[j].x);
            float2 f23 = __half22float2(*(__half2*)&v[j].y);
            acc.x += f01.x; acc.y += f01.y; acc.z += f23.x; acc.w += f23.y;
        }
    }
    for (; k < e; k++) {
        uint2 v = xwh[g_csr[k] * 32 + lane];
        float2 f01 = __half22float2(*(__half2*)&v.x);
        float2 f23 = __half22float2(*(__half2*)&v.y);
        acc.x += f01.x; acc.y += f01.y; acc.z += f23.x; acc.w += f23.y;
    }
    return acc;
}

// layer-1 agg: writes bf16 hi/lo split directly (input of layer-2 GEMM)
__global__ void k_agg_split(const uint2* __restrict__ xwh, const float4* __restrict__ bias4, int n) {
    int warp = threadIdx.x >> 5, lane = threadIdx.x & 31;
    int c = blockIdx.x * 8 + warp;
    if (c >= n) return;
    float4 acc = agg_node(xwh, c, lane);
    float di = g_dinv[c];
    float4 b = bias4[lane];
    float4 o;
    o.x = fmaxf(fmaf(di, acc.x, b.x), 0.f);
    o.y = fmaxf(fmaf(di, acc.y, b.y), 0.f);
    o.z = fmaxf(fmaf(di, acc.z, b.z), 0.f);
    o.w = fmaxf(fmaf(di, acc.w, b.w), 0.f);
    __nv_bfloat162 h01 = __floats2bfloat162_rn(o.x, o.y);
    __nv_bfloat162 h23 = __floats2bfloat162_rn(o.z, o.w);
    float2 f01 = __bfloat1622float2(h01);
    float2 f23 = __bfloat1622float2(h23);
    __nv_bfloat162 l01 = __floats2bfloat162_rn(o.x - f01.x, o.y - f01.y);
    __nv_bfloat162 l23 = __floats2bfloat162_rn(o.z - f23.x, o.w - f23.y);
    __nv_bfloat162* ah = (__nv_bfloat162*)g_ahi;
    __nv_bfloat162* al = (__nv_bfloat162*)g_alo;
    int bi = c * 64 + lane * 2;
    ah[bi] = h01; ah[bi + 1] = h23;
    al[bi] = l01; al[bi + 1] = l23;
}

// layer-2 agg fused with classifier projection: writes only g_p[node*8..+8]
__global__ void k_agg_proj(const uint2* __restrict__ xwh, const float4* __restrict__ bias4,
                           const float* __restrict__ Wfc, int n) {
    __shared__ float W[256 * 4];
    int t = threadIdx.x;
#pragma unroll
    for (int i = 0; i < 4; i++) W[t + 256 * i] = Wfc[t + 256 * i];
    __syncthreads();
    int warp = t >> 5, lane = t & 31;
    int c = blockIdx.x * 8 + warp;
    if (c >= n) return;
    float4 acc = agg_node(xwh, c, lane);
    float di = g_dinv[c];
    float4 b = bias4[lane];
    float4 o;
    o.x = fmaxf(fmaf(di, acc.x, b.x), 0.f);
    o.y = fmaxf(fmaf(di, acc.y, b.y), 0.f);
    o.z = fmaxf(fmaf(di, acc.z, b.z), 0.f);
    o.w = fmaxf(fmaf(di, acc.w, b.w), 0.f);
    // projection: lane holds features f = 4*lane + q (q=0..3)
    int f0 = lane * 4;
    float p[8];
#pragma unroll
    for (int j = 0; j < 4; j++) {
        p[j] = o.x * W[(f0 + 0) * 4 + j] + o.y * W[(f0 + 1) * 4 + j]
             + o.z * W[(f0 + 2) * 4 + j] + o.w * W[(f0 + 3) * 4 + j];
        p[4 + j] = o.x * W[(128 + f0 + 0) * 4 + j] + o.y * W[(128 + f0 + 1) * 4 + j]
                 + o.z * W[(128 + f0 + 2) * 4 + j] + o.w * W[(128 + f0 + 3) * 4 + j];
    }
#pragma unroll
    for (int j = 0; j < 8; j++) {
        float v = p[j];
#pragma unroll
        for (int off = 16; off > 0; off >>= 1) v += __shfl_xor_sync(0xffffffffu, v, off);
        if (lane == j) g_p[c * 8 + j] = v;
    }
}

// -------- edge scoring + log-softmax --------
__global__ void k_edge(const int* __restrict__ ei, const float* __restrict__ bfc,
                       float* __restrict__ out, int E) {
    int e = blockIdx.x * blockDim.x + threadIdx.x;
    if (e >= E) return;
    int r = ei[e];
    int c = ei[E + e];
    float4 pa = *(const float4*)&g_p[r * 8];
    float4 pb = *(const float4*)&g_p[c * 8 + 4];
    float s0 = pa.x + pb.x + bfc[0];
    float s1 = pa.y + pb.y + bfc[1];
    float s2 = pa.z + pb.z + bfc[2];
    float s3 = pa.w + pb.w + bfc[3];
    float m = fmaxf(fmaxf(s0, s1), fmaxf(s2, s3));
    float t0 = expf(s0 - m), t1 = expf(s1 - m), t2 = expf(s2 - m), t3 = expf(s3 - m);
    float l = m + logf(t0 + t1 + t2 + t3);
    *(float4*)&out[e * 4] = make_float4(s0 - l, s1 - l, s2 - l, s3 - l);
}

extern "C" void kernel_launch(void* const* d_in, const int* in_sizes, int n_in,
                              void* d_out, int out_size) {
    const float* x   = (const float*)d_in[0];
    const int*   ei  = (const int*)d_in[1];
    const float* W1  = (const float*)d_in[2];
    const float* b1  = (const float*)d_in[3];
    const float* W2  = (const float*)d_in[4];
    const float* b2  = (const float*)d_in[5];
    const float* Wfc = (const float*)d_in[6];
    const float* bfc = (const float*)d_in[7];
    float* out = (float*)d_out;

    int n = in_sizes[0] / DH;
    int E = in_sizes[1] / 2;
    int E4 = E / 4;

    __half* xwh;
    cudaGetSymbolAddress((void**)&xwh, g_xwh);
    __nv_bfloat16 *b1hi, *b1lo, *b2hi, *b2lo;
    cudaGetSymbolAddress((void**)&b1hi, g_b1hi);
    cudaGetSymbolAddress((void**)&b1lo, g_b1lo);
    cudaGetSymbolAddress((void**)&b2hi, g_b2hi);
    cudaGetSymbolAddress((void**)&b2lo, g_b2lo);

    static int smem_set = 0;
    if (!smem_set) {
        cudaFuncSetAttribute(k_gemm_mma, cudaFuncAttributeMaxDynamicSharedMemorySize, SM_TOTAL);
        smem_set = 1;
    }

    int tb = 256;
    // fused conversions + count zeroing
    k_prep<<<(NN_PAD * 32 + tb - 1) / tb, tb>>>((const float4*)x, W1, W2, n);

    // CSR build
    k_hist<<<(E4 + tb - 1) / tb, tb>>>((const int4*)(ei + E), E4);
    k_bsum<<<SCAN_G, 1024>>>(n);
    k_scan2<<<SCAN_G, 1024>>>(n);
    k_scatter<<<(E4 + tb - 1) / tb, tb>>>((const int4*)ei, (const int4*)(ei + E), E4);

    // layer 1
    k_gemm_mma<<<NN_PAD / 128, 256, SM_TOTAL>>>(xwh, b1hi, b1lo, n);
    k_agg_split<<<(n + 7) / 8, 256>>>((const uint2*)xwh, (const float4*)b1, n);

    // layer 2 (agg fused with classifier projection)
    k_gemm_mma<<<NN_PAD / 128, 256, SM_TOTAL>>>(xwh, b2hi, b2lo, n);
    k_agg_proj<<<(n + 7) / 8, 256>>>((const uint2*)xwh, (const float4*)b2, Wfc, n);

    // edge classifier
    k_edge<<<(E + tb - 1) / tb, tb>>>(ei, bfc, out, E);
}

// round 9
// speedup vs baseline: 1.0152x; 1.0152x over previous
#include <cuda_runtime.h>
#include <cuda_bf16.h>
#include <cuda_fp16.h>
#include <cstdint>

#define NN 50000
#define NN_PAD 50048          // 391 * 128
#define EE 600000
#define DH 128
#define SCAN_G 49             // 49 * 1024 = 50176 >= NN

// -------- device scratch (no allocations allowed) --------
__device__ __half g_xwh[NN * DH];               // A@W (unscaled), fp16
__device__ float g_dinv[NN];
__device__ int   g_count[NN];                   // statically zero; re-zeroed by k_scan2
__device__ int   g_off[NN + 1];
__device__ int   g_cursor[NN];
__device__ int   g_csr[EE];
__device__ int   g_bsum[SCAN_G];
__device__ int   g_bbase[SCAN_G];
__device__ int   g_tick;
__device__ float g_p[NN * 8];
__device__ __nv_bfloat16 g_ahi[NN_PAD * DH];    // bf16 split of current GEMM input
__device__ __nv_bfloat16 g_alo[NN_PAD * DH];
__device__ __nv_bfloat16 g_b1hi[DH * DH];       // bf16 split of W1^T / W2^T
__device__ __nv_bfloat16 g_b1lo[DH * DH];
__device__ __nv_bfloat16 g_b2hi[DH * DH];
__device__ __nv_bfloat16 g_b2lo[DH * DH];

__device__ __forceinline__ uint32_t smem_u32(const void* p) {
    uint32_t a;
    asm("{ .reg .u64 t; cvta.to.shared.u64 t, %1; cvt.u32.u64 %0, t; }" : "=r"(a) : "l"(p));
    return a;
}

// -------- fused prep: x -> bf16 split, W1/W2 -> bf16 split, edge histogram --------
__global__ void k_prep(const float4* __restrict__ x4,
                       const float* __restrict__ W1, const float* __restrict__ W2,
                       const int4* __restrict__ col4, int E4, int n) {
    int i = blockIdx.x * blockDim.x + threadIdx.x;
    if (i < E4) {                                 // histogram (counts start at zero)
        int4 c = col4[i];
        atomicAdd(&g_count[c.x], 1);
        atomicAdd(&g_count[c.y], 1);
        atomicAdd(&g_count[c.z], 1);
        atomicAdd(&g_count[c.w], 1);
    }
    if (i < 2 * DH * DH) {
        int which = i >> 14;
        int j = i & 16383;
        int nIdx = j >> 7, k = j & 127;
        const float* W = which ? W2 : W1;
        float v = W[k * DH + nIdx];               // transpose: B[n][k] = W[k][n]
        __nv_bfloat16 h = __float2bfloat16(v);
        __nv_bfloat16 l = __float2bfloat16(v - __bfloat162float(h));
        if (which) { g_b2hi[j] = h; g_b2lo[j] = l; }
        else       { g_b1hi[j] = h; g_b1lo[j] = l; }
    }
    if (i >= NN_PAD * 32) return;
    int row = i >> 5;
    float4 v = (row < n) ? x4[i] : make_float4(0.f, 0.f, 0.f, 0.f);
    __nv_bfloat162 h01 = __floats2bfloat162_rn(v.x, v.y);
    __nv_bfloat162 h23 = __floats2bfloat162_rn(v.z, v.w);
    float2 f01 = __bfloat1622float2(h01);
    float2 f23 = __bfloat1622float2(h23);
    __nv_bfloat162 l01 = __floats2bfloat162_rn(v.x - f01.x, v.y - f01.y);
    __nv_bfloat162 l23 = __floats2bfloat162_rn(v.z - f23.x, v.w - f23.y);
    __nv_bfloat162* ah = (__nv_bfloat162*)g_ahi;
    __nv_bfloat162* al = (__nv_bfloat162*)g_alo;
    ah[i * 2] = h01; ah[i * 2 + 1] = h23;
    al[i * 2] = l01; al[i * 2 + 1] = l23;
}

// block sums + last-block scan of the 49 block sums (fused)
__global__ void k_bsum(int n) {
    __shared__ int sh[1024];
    int tid = threadIdx.x;
    int i = blockIdx.x * 1024 + tid;
    sh[tid] = (i < n) ? g_count[i] : 0;
    __syncthreads();
#pragma unroll
    for (int o = 512; o > 0; o >>= 1) {
        if (tid < o) sh[tid] += sh[tid + o];
        __syncthreads();
    }
    if (tid == 0) {
        g_bsum[blockIdx.x] = sh[0];
        __threadfence();
        int t = atomicAdd(&g_tick, 1);
        if (t == SCAN_G - 1) {
            g_tick = 0;                       // reset for next graph replay
            int run = 0;
            for (int b = 0; b < SCAN_G; b++) { g_bbase[b] = run; run += g_bsum[b]; }
        }
    }
}

__global__ void k_scan2(int n) {
    __shared__ int sh[1024];
    int tid = threadIdx.x;
    int i = blockIdx.x * 1024 + tid;
    int v = (i < n) ? g_count[i] : 0;
    sh[tid] = v;
    __syncthreads();
#pragma unroll
    for (int o = 1; o < 1024; o <<= 1) {
        int t = (tid >= o) ? sh[tid - o] : 0;
        __syncthreads();
        sh[tid] += t;
        __syncthreads();
    }
    if (i < n) {
        int excl = g_bbase[blockIdx.x] + sh[tid] - v;
        g_off[i] = excl;
        g_cursor[i] = excl;
        g_dinv[i] = rsqrtf((float)(v + 1));
        g_count[i] = 0;                       // restore invariant for next replay
        if (i == n - 1) g_off[n] = excl + v;
    }
}

__global__ void k_scatter(const int4* __restrict__ row4, const int4* __restrict__ col4, int E4) {
    int i = blockIdx.x * blockDim.x + threadIdx.x;
    if (i < E4) {
        int4 c = col4[i];
        int4 r = row4[i];
        g_csr[atomicAdd(&g_cursor[c.x], 1)] = r.x;
        g_csr[atomicAdd(&g_cursor[c.y], 1)] = r.y;
        g_csr[atomicAdd(&g_cursor[c.z], 1)] = r.z;
        g_csr[atomicAdd(&g_cursor[c.w], 1)] = r.w;
    }
}

// ======================= mma.sync (HMMA) GEMM =======================
// xwh[row,:] = fp16( A[row,:] @ W )  (no dinv scaling here; done in the aggs)
#define SM_AHI  0
#define SM_ALO  32768
#define SM_BHI  65536
#define SM_BLO  98304
#define SM_TOTAL 131072

__device__ __forceinline__ void ldm_x4(uint32_t* r, uint32_t addr) {
    asm volatile("ldmatrix.sync.aligned.m8n8.x4.shared.b16 {%0,%1,%2,%3}, [%4];"
                 : "=r"(r[0]), "=r"(r[1]), "=r"(r[2]), "=r"(r[3]) : "r"(addr) : "memory");
}
__device__ __forceinline__ void mma16816(float* c, const uint32_t* a, const uint32_t* b) {
    asm volatile("mma.sync.aligned.m16n8k16.row.col.f32.bf16.bf16.f32 "
                 "{%0,%1,%2,%3}, {%4,%5,%6,%7}, {%8,%9}, {%0,%1,%2,%3};"
                 : "+f"(c[0]), "+f"(c[1]), "+f"(c[2]), "+f"(c[3])
                 : "r"(a[0]), "r"(a[1]), "r"(a[2]), "r"(a[3]), "r"(b[0]), "r"(b[1]));
}
__device__ __forceinline__ uint32_t sw_off(int row, int chunk) {
    int phys = (chunk & 8) | ((chunk ^ row) & 7);
    return (uint32_t)(row * 256 + phys * 16);
}

__global__ void __launch_bounds__(256, 1) k_gemm_mma(
        __half* __restrict__ C,
        const __nv_bfloat16* __restrict__ bhi,
        const __nv_bfloat16* __restrict__ blo, int n) {
    extern __shared__ char smem[];
    uint32_t sb = smem_u32(smem);
    int tid = threadIdx.x, wid = tid >> 5, lane = tid & 31;
    int row0 = blockIdx.x * 128;

    {
        const __nv_bfloat16* srcs[4] = { g_ahi + (size_t)row0 * DH, g_alo + (size_t)row0 * DH,
                                         bhi, blo };
        const int bases[4] = { SM_AHI, SM_ALO, SM_BHI, SM_BLO };
#pragma unroll
        for (int t4 = 0; t4 < 4; t4++) {
            const uint4* src = (const uint4*)srcs[t4];
#pragma unroll
            for (int j = 0; j < 8; j++) {
                int f = tid + 256 * j;          // 0..2047
                int row = f >> 4;
                int chunk = f & 15;
                *(uint4*)(smem + bases[t4] + sw_off(row, chunk)) = src[row * 16 + chunk];
            }
        }
    }
    __syncthreads();

    int warp_m = wid & 3;
    int warp_n = wid >> 2;
    int lr = lane & 7;
    int rowA0 = warp_m * 32 + ((lane >> 3) & 1) * 8 + lr;
    int aHi = lane >> 4;
    int rowB0 = warp_n * 64 + ((lane >> 4) & 1) * 8 + lr;
    int bHi = (lane >> 3) & 1;

    float c[2][8][4];
#pragma unroll
    for (int mt = 0; mt < 2; mt++)
#pragma unroll
        for (int nt = 0; nt < 8; nt++)
#pragma unroll
            for (int q = 0; q < 4; q++) c[mt][nt][q] = 0.f;

#pragma unroll
    for (int p = 0; p < 3; p++) {
        uint32_t aBase = sb + (p == 2 ? SM_ALO : SM_AHI);
        uint32_t bBase = sb + (p == 1 ? SM_BLO : SM_BHI);
#pragma unroll
        for (int ks = 0; ks < 8; ks++) {
            uint32_t a[2][4];
#pragma unroll
            for (int mt = 0; mt < 2; mt++)
                ldm_x4(a[mt], aBase + sw_off(rowA0 + mt * 16, ks * 2 + aHi));
            uint32_t b[8][2];
#pragma unroll
            for (int nt2 = 0; nt2 < 4; nt2++) {
                uint32_t r[4];
                ldm_x4(r, bBase + sw_off(rowB0 + nt2 * 16, ks * 2 + bHi));
                b[2 * nt2][0] = r[0]; b[2 * nt2][1] = r[1];
                b[2 * nt2 + 1][0] = r[2]; b[2 * nt2 + 1][1] = r[3];
            }
#pragma unroll
            for (int mt = 0; mt < 2; mt++)
#pragma unroll
                for (int nt = 0; nt < 8; nt++)
                    mma16816(c[mt][nt], a[mt], b[nt]);
        }
    }

#pragma unroll
    for (int mt = 0; mt < 2; mt++) {
        int row = row0 + warp_m * 32 + mt * 16 + (lane >> 2);
        int col = warp_n * 64 + (lane & 3) * 2;
#pragma unroll
        for (int nt = 0; nt < 8; nt++) {
            int cc = col + nt * 8;
            if (row < n)
                *(__half2*)&C[(size_t)row * DH + cc] =
                    __floats2half2_rn(c[mt][nt][0], c[mt][nt][1]);
            if (row + 8 < n)
                *(__half2*)&C[(size_t)(row + 8) * DH + cc] =
                    __floats2half2_rn(c[mt][nt][2], c[mt][nt][3]);
        }
    }
}

// -------- aggregation core: one warp per node, fp16 rows, fp32 accum, dinv applied here --------
__device__ __forceinline__ float4 agg_node(const uint2* __restrict__ xwh, int c, int lane,
                                           float dic) {
    uint2 sv = xwh[c * 32 + lane];                 // self-loop term (weight dinv[c])
    float2 a01 = __half22float2(*(__half2*)&sv.x);
    float2 a23 = __half22float2(*(__half2*)&sv.y);
    float4 acc = make_float4(dic * a01.x, dic * a01.y, dic * a23.x, dic * a23.y);
    int s = g_off[c], e = g_off[c + 1];
    int k = s;
    for (; k + 8 <= e; k += 8) {
        int r[8];
#pragma unroll
        for (int j = 0; j < 8; j++) r[j] = g_csr[k + j];
        uint2 v[8];
        float d[8];
#pragma unroll
        for (int j = 0; j < 8; j++) { v[j] = xwh[r[j] * 32 + lane]; d[j] = g_dinv[r[j]]; }
#pragma unroll
        for (int j = 0; j < 8; j++) {
            float2 f01 = __half22float2(*(__half2*)&v[j].x);
            float2 f23 = __half22float2(*(__half2*)&v[j].y);
            acc.x = fmaf(d[j], f01.x, acc.x);
            acc.y = fmaf(d[j], f01.y, acc.y);
            acc.z = fmaf(d[j], f23.x, acc.z);
            acc.w = fmaf(d[j], f23.y, acc.w);
        }
    }
    for (; k < e; k++) {
        int r = g_csr[k];
        uint2 v = xwh[r * 32 + lane];
        float d = g_dinv[r];
        float2 f01 = __half22float2(*(__half2*)&v.x);
        float2 f23 = __half22float2(*(__half2*)&v.y);
        acc.x = fmaf(d, f01.x, acc.x);
        acc.y = fmaf(d, f01.y, acc.y);
        acc.z = fmaf(d, f23.x, acc.z);
        acc.w = fmaf(d, f23.y, acc.w);
    }
    return acc;
}

// layer-1 agg: writes bf16 hi/lo split directly (input of layer-2 GEMM)
__global__ void k_agg_split(const uint2* __restrict__ xwh, const float4* __restrict__ bias4, int n) {
    int warp = threadIdx.x >> 5, lane = threadIdx.x & 31;
    int c = blockIdx.x * 8 + warp;
    if (c >= n) return;
    float di = g_dinv[c];
    float4 acc = agg_node(xwh, c, lane, di);
    float4 b = bias4[lane];
    float4 o;
    o.x = fmaxf(fmaf(di, acc.x, b.x), 0.f);
    o.y = fmaxf(fmaf(di, acc.y, b.y), 0.f);
    o.z = fmaxf(fmaf(di, acc.z, b.z), 0.f);
    o.w = fmaxf(fmaf(di, acc.w, b.w), 0.f);
    __nv_bfloat162 h01 = __floats2bfloat162_rn(o.x, o.y);
    __nv_bfloat162 h23 = __floats2bfloat162_rn(o.z, o.w);
    float2 f01 = __bfloat1622float2(h01);
    float2 f23 = __bfloat1622float2(h23);
    __nv_bfloat162 l01 = __floats2bfloat162_rn(o.x - f01.x, o.y - f01.y);
    __nv_bfloat162 l23 = __floats2bfloat162_rn(o.z - f23.x, o.w - f23.y);
    __nv_bfloat162* ah = (__nv_bfloat162*)g_ahi;
    __nv_bfloat162* al = (__nv_bfloat162*)g_alo;
    int bi = c * 64 + lane * 2;
    ah[bi] = h01; ah[bi + 1] = h23;
    al[bi] = l01; al[bi + 1] = l23;
}

// layer-2 agg fused with classifier projection: writes only g_p[node*8..+8]
__global__ void k_agg_proj(const uint2* __restrict__ xwh, const float4* __restrict__ bias4,
                           const float* __restrict__ Wfc, int n) {
    __shared__ float W[256 * 4];
    int t = threadIdx.x;
#pragma unroll
    for (int i = 0; i < 4; i++) W[t + 256 * i] = Wfc[t + 256 * i];
    __syncthreads();
    int warp = t >> 5, lane = t & 31;
    int c = blockIdx.x * 8 + warp;
    if (c >= n) return;
    float di = g_dinv[c];
    float4 acc = agg_node(xwh, c, lane, di);
    float4 b = bias4[lane];
    float4 o;
    o.x = fmaxf(fmaf(di, acc.x, b.x), 0.f);
    o.y = fmaxf(fmaf(di, acc.y, b.y), 0.f);
    o.z = fmaxf(fmaf(di, acc.z, b.z), 0.f);
    o.w = fmaxf(fmaf(di, acc.w, b.w), 0.f);
    int f0 = lane * 4;
    float p[8];
#pragma unroll
    for (int j = 0; j < 4; j++) {
        p[j] = o.x * W[(f0 + 0) * 4 + j] + o.y * W[(f0 + 1) * 4 + j]
             + o.z * W[(f0 + 2) * 4 + j] + o.w * W[(f0 + 3) * 4 + j];
        p[4 + j] = o.x * W[(128 + f0 + 0) * 4 + j] + o.y * W[(128 + f0 + 1) * 4 + j]
                 + o.z * W[(128 + f0 + 2) * 4 + j] + o.w * W[(128 + f0 + 3) * 4 + j];
    }
#pragma unroll
    for (int j = 0; j < 8; j++) {
        float v = p[j];
#pragma unroll
        for (int off = 16; off > 0; off >>= 1) v += __shfl_xor_sync(0xffffffffu, v, off);
        if (lane == j) g_p[c * 8 + j] = v;
    }
}

// -------- edge scoring + log-softmax --------
__global__ void k_edge(const int* __restrict__ ei, const float* __restrict__ bfc,
                       float* __restrict__ out, int E) {
    int e = blockIdx.x * blockDim.x + threadIdx.x;
    if (e >= E) return;
    int r = ei[e];
    int c = ei[E + e];
    float4 pa = *(const float4*)&g_p[r * 8];
    float4 pb = *(const float4*)&g_p[c * 8 + 4];
    float s0 = pa.x + pb.x + bfc[0];
    float s1 = pa.y + pb.y + bfc[1];
    float s2 = pa.z + pb.z + bfc[2];
    float s3 = pa.w + pb.w + bfc[3];
    float m = fmaxf(fmaxf(s0, s1), fmaxf(s2, s3));
    float t0 = expf(s0 - m), t1 = expf(s1 - m), t2 = expf(s2 - m), t3 = expf(s3 - m);
    float l = m + logf(t0 + t1 + t2 + t3);
    *(float4*)&out[e * 4] = make_float4(s0 - l, s1 - l, s2 - l, s3 - l);
}

extern "C" void kernel_launch(void* const* d_in, const int* in_sizes, int n_in,
                              void* d_out, int out_size) {
    const float* x   = (const float*)d_in[0];
    const int*   ei  = (const int*)d_in[1];
    const float* W1  = (const float*)d_in[2];
    const float* b1  = (const float*)d_in[3];
    const float* W2  = (const float*)d_in[4];
    const float* b2  = (const float*)d_in[5];
    const float* Wfc = (const float*)d_in[6];
    const float* bfc = (const float*)d_in[7];
    float* out = (float*)d_out;

    int n = in_sizes[0] / DH;
    int E = in_sizes[1] / 2;
    int E4 = E / 4;

    __half* xwh;
    cudaGetSymbolAddress((void**)&xwh, g_xwh);
    __nv_bfloat16 *b1hi, *b1lo, *b2hi, *b2lo;
    cudaGetSymbolAddress((void**)&b1hi, g_b1hi);
    cudaGetSymbolAddress((void**)&b1lo, g_b1lo);
    cudaGetSymbolAddress((void**)&b2hi, g_b2hi);
    cudaGetSymbolAddress((void**)&b2lo, g_b2lo);

    static cudaStream_t s2;
    static cudaEvent_t evA, evB;
    static int init_done = 0;
    if (!init_done) {
        cudaFuncSetAttribute(k_gemm_mma, cudaFuncAttributeMaxDynamicSharedMemorySize, SM_TOTAL);
        cudaStreamCreateWithFlags(&s2, cudaStreamNonBlocking);
        cudaEventCreateWithFlags(&evA, cudaEventDisableTiming);
        cudaEventCreateWithFlags(&evB, cudaEventDisableTiming);
        init_done = 1;
    }

    int tb = 256;
    // prep: conversions + histogram (counts are zero by invariant)
    k_prep<<<(NN_PAD * 32 + tb - 1) / tb, tb>>>((const float4*)x, W1, W2,
                                                (const int4*)(ei + E), E4, n);
    // fork: CSR chain on s2, GEMM1 on stream 0 — independent
    cudaEventRecord(evA, 0);
    cudaStreamWaitEvent(s2, evA, 0);
    k_bsum<<<SCAN_G, 1024, 0, s2>>>(n);
    k_scan2<<<SCAN_G, 1024, 0, s2>>>(n);
    k_scatter<<<(E4 + tb - 1) / tb, tb, 0, s2>>>((const int4*)ei, (const int4*)(ei + E), E4);
    cudaEventRecord(evB, s2);

    k_gemm_mma<<<NN_PAD / 128, 256, SM_TOTAL>>>(xwh, b1hi, b1lo, n);   // stream 0, overlaps s2

    // join: agg1 needs CSR + dinv + GEMM1
    cudaStreamWaitEvent(0, evB, 0);
    k_agg_split<<<(n + 7) / 8, 256>>>((const uint2*)xwh, (const float4*)b1, n);

    // layer 2
    k_gemm_mma<<<NN_PAD / 128, 256, SM_TOTAL>>>(xwh, b2hi, b2lo, n);
    k_agg_proj<<<(n + 7) / 8, 256>>>((const uint2*)xwh, (const float4*)b2, Wfc, n);

    // edge classifier
    k_edge<<<(E + tb - 1) / tb, tb>>>(ei, bfc, out, E);
}